// round 4
// baseline (speedup 1.0000x reference)
#include <cuda_runtime.h>
#include <cuda_bf16.h>
#include <cstdint>

#define NTOK   8192
#define DIM    1024
#define NEXP   8
#define CAP    1024
#define LN_EPS 1e-5f

// Arch-specific feature gate: tcgen05 only exists on sm_100a/sm_103a targets.
#if defined(__CUDA_ARCH_FEAT_SM103_ALL) || defined(__CUDA_ARCH_FEAT_SM100_ALL)
#define HAS_TCGEN05 1
#else
#define HAS_TCGEN05 0
#endif

// ---------------- scratch (device globals: no allocation) -------------------
__device__ __nv_bfloat16 g_xhi[NTOK * DIM];
__device__ __nv_bfloat16 g_xlo[NTOK * DIM];
__device__ __nv_bfloat16 g_whi[NEXP * DIM * DIM];   // transposed: [e][n][k]
__device__ __nv_bfloat16 g_wlo[NEXP * DIM * DIM];
__device__ float         g_h  [NTOK * DIM];

// ---------------- PTX helpers (guarded) -------------------------------------
#if HAS_TCGEN05
__device__ __forceinline__ uint32_t smem_u32(const void* p) {
    uint32_t a;
    asm("{ .reg .u64 t; cvta.to.shared.u64 t, %1; cvt.u32.u64 %0, t; }" : "=r"(a) : "l"(p));
    return a;
}
__device__ __forceinline__ uint32_t elect_one_pred() {
    uint32_t p;
    asm volatile("{\n\t.reg .pred p;\n\telect.sync _|p, 0xFFFFFFFF;\n\tselp.b32 %0, 1, 0, p;\n\t}" : "=r"(p));
    return p;
}

#define CP_ASYNC16(dst_u32, src_ptr) \
    asm volatile("cp.async.cg.shared.global [%0], [%1], 16;" :: "r"(dst_u32), "l"(src_ptr) : "memory")
#define CP_COMMIT() asm volatile("cp.async.commit_group;" ::: "memory")
#define CP_WAIT1()  asm volatile("cp.async.wait_group 1;" ::: "memory")
#define CP_WAIT0()  asm volatile("cp.async.wait_group 0;" ::: "memory")

#define MBARRIER_INIT(addr, cnt) \
    asm volatile("mbarrier.init.shared.b64 [%0], %1;" :: "r"(addr), "r"(cnt) : "memory")
#define MBARRIER_INVAL(addr) \
    asm volatile("mbarrier.inval.shared.b64 [%0];" :: "r"(addr) : "memory")
#define MBARRIER_WAIT_PARITY(addr, par) do {                                        \
    uint32_t _m = (addr), _p = (par), _d;                                           \
    asm volatile("{\n\t.reg .pred p;\n\t"                                           \
        "mbarrier.try_wait.parity.acquire.cta.shared::cta.b64 p, [%1], %2;\n\t"     \
        "selp.b32 %0, 1, 0, p;\n\t}" : "=r"(_d) : "r"(_m), "r"(_p) : "memory");     \
    if (!_d) {                                                                      \
        asm volatile("{\n\t.reg .pred P1;\n\t"                                      \
            "WL_%=:\n\t"                                                            \
            "mbarrier.try_wait.parity.acquire.cta.shared::cta.b64 P1, [%0], %1, 0x989680;\n\t" \
            "@P1 bra.uni WD_%=;\n\tbra.uni WL_%=;\n\tWD_%=:\n\t}"                   \
            :: "r"(_m), "r"(_p) : "memory");                                        \
    } } while (0)

#define TCGEN05_ALLOC(smem_addr, ncols) \
    asm volatile("tcgen05.alloc.cta_group::1.sync.aligned.shared::cta.b32 [%0], %1;" \
                 :: "r"(smem_addr), "r"(ncols) : "memory")
#define TCGEN05_DEALLOC(tmem, ncols) \
    asm volatile("tcgen05.dealloc.cta_group::1.sync.aligned.b32 %0, %1;" :: "r"(tmem), "r"(ncols))
#define TCGEN05_RELINQ() \
    asm volatile("tcgen05.relinquish_alloc_permit.cta_group::1.sync.aligned;")
#define TCGEN05_COMMIT(mbar) \
    asm volatile("tcgen05.commit.cta_group::1.mbarrier::arrive::one.shared::cluster.b64 [%0];" \
                 :: "r"(mbar) : "memory")
#define TCGEN05_FENCE_AFTER() \
    asm volatile("tcgen05.fence::after_thread_sync;" ::: "memory")
#define TCGEN05_FENCE_BEFORE() \
    asm volatile("tcgen05.fence::before_thread_sync;" ::: "memory")
#define TCGEN05_WAIT_LD() \
    asm volatile("tcgen05.wait::ld.sync.aligned;" ::: "memory")
#define FENCE_PROXY_ASYNC() \
    asm volatile("fence.proxy.async.shared::cta;" ::: "memory")

#define TCGEN05_LD_X32(r, tmem_addr) \
    asm volatile("tcgen05.ld.sync.aligned.32x32b.x32.b32 " \
        "{%0, %1, %2, %3, %4, %5, %6, %7, %8, %9, %10, %11, %12, %13, %14, %15, " \
        " %16, %17, %18, %19, %20, %21, %22, %23, %24, %25, %26, %27, %28, %29, %30, %31}, [%32];" \
        : "=r"((r)[0]),  "=r"((r)[1]),  "=r"((r)[2]),  "=r"((r)[3]),  \
          "=r"((r)[4]),  "=r"((r)[5]),  "=r"((r)[6]),  "=r"((r)[7]),  \
          "=r"((r)[8]),  "=r"((r)[9]),  "=r"((r)[10]), "=r"((r)[11]), \
          "=r"((r)[12]), "=r"((r)[13]), "=r"((r)[14]), "=r"((r)[15]), \
          "=r"((r)[16]), "=r"((r)[17]), "=r"((r)[18]), "=r"((r)[19]), \
          "=r"((r)[20]), "=r"((r)[21]), "=r"((r)[22]), "=r"((r)[23]), \
          "=r"((r)[24]), "=r"((r)[25]), "=r"((r)[26]), "=r"((r)[27]), \
          "=r"((r)[28]), "=r"((r)[29]), "=r"((r)[30]), "=r"((r)[31]) \
        : "r"(tmem_addr))

// SS-mode bf16 MMA, cta_group::1, fp32 accumulate in TMEM
__device__ __forceinline__ void mma_f16_ss(uint32_t d_tmem, uint64_t a_desc,
                                           uint64_t b_desc, uint32_t idesc, bool acc) {
    uint32_t en = acc ? 1u : 0u, z = 0u;
    asm volatile("{\n\t.reg .pred p;\n\tsetp.ne.u32 p, %5, 0;\n\t"
        "tcgen05.mma.cta_group::1.kind::f16 [%0], %1, %2, %3, {%4, %4, %4, %4}, p;\n\t}"
        :: "r"(d_tmem), "l"(a_desc), "l"(b_desc), "r"(idesc), "r"(z), "r"(en) : "memory");
}

// SW128 K-major descriptor (LBO=1, SBO=64, version=1, layout=SW128)
static __device__ __forceinline__ uint64_t make_desc(uint32_t addr) {
    const uint64_t BASE = (2ull << 61) | (1ull << 46) | (64ull << 32) | (1ull << 16);
    return BASE | ((uint64_t)(addr >> 4) & 0x3FFFull);
}

// idesc: F32 out, BF16 in, M=128, N=256
#define MMA_IDESC ((1u << 4) | (1u << 7) | (1u << 10) | ((256u / 8) << 17) | ((128u / 16) << 24))
#endif // HAS_TCGEN05

// ---------------------------------------------------------------------------
// Conversion: X fp32 -> (hi, lo) bf16
// ---------------------------------------------------------------------------
__global__ __launch_bounds__(256)
void convert_x_kernel(const float* __restrict__ X,
                      __nv_bfloat16* __restrict__ Xhi,
                      __nv_bfloat16* __restrict__ Xlo)
{
    int idx = blockIdx.x * 256 + threadIdx.x;       // float4 index
    float4 v = ((const float4*)X)[idx];
    __nv_bfloat16 h[4], l[4];
    float vv[4] = {v.x, v.y, v.z, v.w};
    #pragma unroll
    for (int i = 0; i < 4; ++i) {
        h[i] = __float2bfloat16(vv[i]);
        l[i] = __float2bfloat16(vv[i] - __bfloat162float(h[i]));
    }
    *(uint2*)(Xhi + (size_t)idx * 4) = *(uint2*)h;
    *(uint2*)(Xlo + (size_t)idx * 4) = *(uint2*)l;
}

// ---------------------------------------------------------------------------
// Conversion + transpose: W[e][k][n] fp32 -> Wt(hi/lo)[e][n][k] bf16
// ---------------------------------------------------------------------------
__global__ __launch_bounds__(256)
void convert_w_kernel(const float* __restrict__ W,
                      __nv_bfloat16* __restrict__ Whi,
                      __nv_bfloat16* __restrict__ Wlo)
{
    __shared__ float t[32][33];
    const int e  = blockIdx.z;
    const int k0 = blockIdx.y * 32;
    const int n0 = blockIdx.x * 32;
    const int tx = threadIdx.x & 31;
    const int ty = threadIdx.x >> 5;    // 0..7

    const float* Wp = W + (size_t)e * DIM * DIM;
    #pragma unroll
    for (int r = 0; r < 4; ++r) {
        int k = k0 + ty + 8 * r;
        t[ty + 8 * r][tx] = Wp[(size_t)k * DIM + n0 + tx];
    }
    __syncthreads();
    #pragma unroll
    for (int r = 0; r < 4; ++r) {
        int n = n0 + ty + 8 * r;
        float v = t[tx][ty + 8 * r];
        __nv_bfloat16 h = __float2bfloat16(v);
        __nv_bfloat16 l = __float2bfloat16(v - __bfloat162float(h));
        size_t off = (size_t)e * DIM * DIM + (size_t)n * DIM + k0 + tx;
        Whi[off] = h;
        Wlo[off] = l;
    }
}

// ---------------------------------------------------------------------------
// GEMM: per expert e, H = relu(X_e @ W_e + b_e).
//   sm_103a image: tcgen05 + cp.async pipeline, bf16x3 split, M=128 N=256.
//   family image : fp32 FFMA fallback (correct, slower).
// ---------------------------------------------------------------------------
#define K_CHUNK   64
#define N_CHUNKS  16               // 1024 / 64
#define BUF_BYTES (96 * 1024)      // Ahi 16K + Alo 16K + Bhi 32K + Blo 32K
#define OFF_A_HI  0
#define OFF_A_LO  16384
#define OFF_B_HI  32768
#define OFF_B_LO  65536
#define OFF_BIAS  (2 * BUF_BYTES)           // 196608, 1KB
#define OFF_TPTR  (OFF_BIAS + 1024)
#define OFF_MBAR0 (OFF_TPTR + 16)
#define OFF_MBAR1 (OFF_MBAR0 + 8)
#define SMEM_SIZE (OFF_MBAR1 + 8)

__global__ __launch_bounds__(256, 1)
void gemm_tc_kernel(const __nv_bfloat16* __restrict__ Xhi,
                    const __nv_bfloat16* __restrict__ Xlo,
                    const __nv_bfloat16* __restrict__ Whi,
                    const __nv_bfloat16* __restrict__ Wlo,
                    const float* __restrict__ bias,
                    float* __restrict__ H)
{
#if HAS_TCGEN05
    extern __shared__ __align__(1024) char smem[];
    const uint32_t sbase  = smem_u32(smem);
    const int e      = blockIdx.z;
    const int tile_n = blockIdx.x * 256;
    const int tile_m = blockIdx.y * 128;
    const int tid    = threadIdx.x;
    const int wid    = tid >> 5;
    const int lid    = tid & 31;

    if (wid == 0) {
        TCGEN05_ALLOC(sbase + OFF_TPTR, 256);
        TCGEN05_RELINQ();
    }
    if (tid == 0) {
        MBARRIER_INIT(sbase + OFF_MBAR0, 1);
        MBARRIER_INIT(sbase + OFF_MBAR1, 1);
    }
    ((float*)(smem + OFF_BIAS))[tid] = bias[e * DIM + tile_n + tid];
    __syncthreads();
    uint32_t tmem;
    asm volatile("ld.shared.b32 %0, [%1];" : "=r"(tmem) : "r"(sbase + OFF_TPTR));

    const __nv_bfloat16* Ah = Xhi + (size_t)(e * CAP + tile_m) * DIM;
    const __nv_bfloat16* Al = Xlo + (size_t)(e * CAP + tile_m) * DIM;
    const __nv_bfloat16* Bh = Whi + ((size_t)e * DIM + tile_n) * DIM;
    const __nv_bfloat16* Bl = Wlo + ((size_t)e * DIM + tile_n) * DIM;

    // per-thread load slices (precomputed): A granule g in [0,1024), B g in [0,2048)
    const int rA  = tid >> 1;                 // A rows: 2 threads per row, 4 granules each
    const int cA0 = (tid & 1) * 4;
    const int rB  = tid;                      // B rows 0..255, 8 granules each
    // issue loads of one chunk into buffer b (0/1) via cp.async
    auto issue_chunk = [&](int c, int b) {
        const uint32_t bb = sbase + b * BUF_BYTES;
        const int k0 = c * K_CHUNK;
        #pragma unroll
        for (int i = 0; i < 4; ++i) {
            int cg = cA0 + i;
            int sw = rA * 128 + ((cg ^ (rA & 7)) << 4);
            CP_ASYNC16(bb + OFF_A_HI + sw, (const char*)(Ah + (size_t)rA * DIM + k0) + cg * 16);
            CP_ASYNC16(bb + OFF_A_LO + sw, (const char*)(Al + (size_t)rA * DIM + k0) + cg * 16);
        }
        #pragma unroll
        for (int cg = 0; cg < 8; ++cg) {
            int sw = rB * 128 + ((cg ^ (rB & 7)) << 4);
            CP_ASYNC16(bb + OFF_B_HI + sw, (const char*)(Bh + (size_t)rB * DIM + k0) + cg * 16);
            CP_ASYNC16(bb + OFF_B_LO + sw, (const char*)(Bl + (size_t)rB * DIM + k0) + cg * 16);
        }
        CP_COMMIT();
    };

    issue_chunk(0, 0);
    issue_chunk(1, 1);

    for (int c = 0; c < N_CHUNKS; ++c) {
        if (c < N_CHUNKS - 1) { CP_WAIT1(); } else { CP_WAIT0(); }
        __syncthreads();                         // chunk c resident for all threads

        if (wid == 0 && elect_one_pred()) {
            FENCE_PROXY_ASYNC();
            uint32_t bb = sbase + (c & 1) * BUF_BYTES;
            uint64_t dAh = make_desc(bb + OFF_A_HI);
            uint64_t dAl = make_desc(bb + OFF_A_LO);
            uint64_t dBh = make_desc(bb + OFF_B_HI);
            uint64_t dBl = make_desc(bb + OFF_B_LO);
            #pragma unroll
            for (int kk = 0; kk < 4; ++kk) {     // K=16 steps (+2 units = 32B)
                mma_f16_ss(tmem, dAh + kk * 2, dBh + kk * 2, MMA_IDESC, !(c == 0 && kk == 0));
                mma_f16_ss(tmem, dAh + kk * 2, dBl + kk * 2, MMA_IDESC, true);
                mma_f16_ss(tmem, dAl + kk * 2, dBh + kk * 2, MMA_IDESC, true);
            }
            TCGEN05_COMMIT(sbase + ((c & 1) ? OFF_MBAR1 : OFF_MBAR0));
        }

        if (c + 2 < N_CHUNKS) {
            // safe to overwrite buffer (c&1) only after MMA chunk c completes
            uint32_t mb = sbase + ((c & 1) ? OFF_MBAR1 : OFF_MBAR0);
            MBARRIER_WAIT_PARITY(mb, (c >> 1) & 1);
            issue_chunk(c + 2, c & 1);
        }
    }

    // drain: chunks 14,15 are commits #7 on each mbar (phase 7, parity 1)
    MBARRIER_WAIT_PARITY(sbase + OFF_MBAR0, 1);
    MBARRIER_WAIT_PARITY(sbase + OFF_MBAR1, 1);
    TCGEN05_FENCE_AFTER();

    // epilogue: warps 0-3 read TMEM (32-lane subpartition = 32 M rows each)
    if (wid < 4) {
        const int row = tile_m + wid * 32 + lid;
        float* outp = H + (size_t)(e * CAP + row) * DIM + tile_n;
        const float* bs = (const float*)(smem + OFF_BIAS);
        #pragma unroll
        for (int base = 0; base < 256; base += 32) {
            uint32_t r[32];
            TCGEN05_LD_X32(r, tmem + base);
            TCGEN05_WAIT_LD();
            float v[32];
            #pragma unroll
            for (int i = 0; i < 32; ++i)
                v[i] = fmaxf(__uint_as_float(r[i]) + bs[base + i], 0.f);
            #pragma unroll
            for (int q = 0; q < 8; ++q)
                *(float4*)(outp + base + q * 4) = *(float4*)&v[q * 4];
        }
        TCGEN05_FENCE_BEFORE();
    }
    __syncthreads();
    if (tid == 0) { MBARRIER_INVAL(sbase + OFF_MBAR0); MBARRIER_INVAL(sbase + OFF_MBAR1); }
    __syncthreads();
    if (wid == 0) TCGEN05_DEALLOC(tmem, 256);

#else
    // ---------------- fp32 FFMA fallback (family-level image) ----------------
    extern __shared__ __align__(1024) char smem_raw[];
    float* As = (float*)smem_raw;                  // [16][128]
    float* Bs = (float*)(smem_raw + 16 * 128 * 4); // [16][256]

    const int e      = blockIdx.z;
    const int tile_n = blockIdx.x * 256;
    const int tile_m = blockIdx.y * 128;
    const int tid    = threadIdx.x;
    const int tx     = tid & 15;     // n: 16 cols each
    const int ty     = tid >> 4;     // m: 8 rows each

    const __nv_bfloat16* Ah = Xhi + (size_t)(e * CAP + tile_m) * DIM;
    const __nv_bfloat16* Al = Xlo + (size_t)(e * CAP + tile_m) * DIM;
    const __nv_bfloat16* Bh = Whi + ((size_t)e * DIM + tile_n) * DIM;
    const __nv_bfloat16* Bl = Wlo + ((size_t)e * DIM + tile_n) * DIM;

    float acc[8][16];
    #pragma unroll
    for (int i = 0; i < 8; ++i)
        #pragma unroll
        for (int j = 0; j < 16; ++j) acc[i][j] = 0.f;

    for (int k0 = 0; k0 < DIM; k0 += 16) {
        #pragma unroll
        for (int it = 0; it < 8; ++it) {          // A: 128x16
            int g = tid + it * 256;
            int r = g >> 4, kc = g & 15;
            As[kc * 128 + r] = __bfloat162float(Ah[(size_t)r * DIM + k0 + kc]) +
                               __bfloat162float(Al[(size_t)r * DIM + k0 + kc]);
        }
        #pragma unroll
        for (int it = 0; it < 16; ++it) {         // B: 256(n) x16(k)
            int g = tid + it * 256;
            int n = g >> 4, kc = g & 15;
            Bs[kc * 256 + n] = __bfloat162float(Bh[(size_t)n * DIM + k0 + kc]) +
                               __bfloat162float(Bl[(size_t)n * DIM + k0 + kc]);
        }
        __syncthreads();
        #pragma unroll
        for (int kc = 0; kc < 16; ++kc) {
            float a[8], b[16];
            #pragma unroll
            for (int i = 0; i < 8; ++i)  a[i] = As[kc * 128 + ty * 8 + i];
            #pragma unroll
            for (int j = 0; j < 16; ++j) b[j] = Bs[kc * 256 + tx * 16 + j];
            #pragma unroll
            for (int i = 0; i < 8; ++i)
                #pragma unroll
                for (int j = 0; j < 16; ++j)
                    acc[i][j] = fmaf(a[i], b[j], acc[i][j]);
        }
        __syncthreads();
    }

    #pragma unroll
    for (int i = 0; i < 8; ++i) {
        int row = tile_m + ty * 8 + i;
        float* outp = H + (size_t)(e * CAP + row) * DIM + tile_n + tx * 16;
        #pragma unroll
        for (int j = 0; j < 16; ++j) {
            float bv = bias[e * DIM + tile_n + tx * 16 + j];
            outp[j] = fmaxf(acc[i][j] + bv, 0.f);
        }
    }
#endif
}

// ---------------------------------------------------------------------------
// LayerNorm: 4 rows per 256-thread CTA, 64 threads per row, MLP=4.
// ---------------------------------------------------------------------------
__global__ __launch_bounds__(256)
void layernorm_kernel(const float* __restrict__ H,
                      const float* __restrict__ gamma,
                      const float* __restrict__ beta,
                      float* __restrict__ out)
{
    const int tid   = threadIdx.x;
    const int r     = tid >> 6;                 // 0..3 (row within block)
    const int lane  = tid & 63;
    const int row   = blockIdx.x * 4 + r;
    const int e     = row >> 10;
    const int col0  = lane * 16;

    const float* h = H + (size_t)row * DIM + col0;
    float4 v[4];
    #pragma unroll
    for (int q = 0; q < 4; ++q) v[q] = *(const float4*)(h + q * 4);

    float s = 0.f, sq = 0.f;
    #pragma unroll
    for (int q = 0; q < 4; ++q) {
        s  += v[q].x + v[q].y + v[q].z + v[q].w;
        sq += v[q].x * v[q].x + v[q].y * v[q].y + v[q].z * v[q].z + v[q].w * v[q].w;
    }

    #pragma unroll
    for (int off = 16; off > 0; off >>= 1) {
        s  += __shfl_xor_sync(0xffffffffu, s,  off);
        sq += __shfl_xor_sync(0xffffffffu, sq, off);
    }

    __shared__ float red_s[8], red_q[8];
    const int wid = tid >> 5;
    if ((tid & 31) == 0) { red_s[wid] = s; red_q[wid] = sq; }
    __syncthreads();

    const float ts = red_s[2 * r] + red_s[2 * r + 1];
    const float tq = red_q[2 * r] + red_q[2 * r + 1];
    const float mean = ts * (1.f / DIM);
    const float var  = tq * (1.f / DIM) - mean * mean;
    const float rstd = rsqrtf(var + LN_EPS);

    const float* gp = gamma + (size_t)e * DIM + col0;
    const float* bp = beta  + (size_t)e * DIM + col0;
    float*       op = out   + (size_t)row * DIM + col0;
    #pragma unroll
    for (int q = 0; q < 4; ++q) {
        float4 g  = *(const float4*)(gp + q * 4);
        float4 bt = *(const float4*)(bp + q * 4);
        float4 o;
        o.x = (v[q].x - mean) * rstd * g.x + bt.x;
        o.y = (v[q].y - mean) * rstd * g.y + bt.y;
        o.z = (v[q].z - mean) * rstd * g.z + bt.z;
        o.w = (v[q].w - mean) * rstd * g.w + bt.w;
        *(float4*)(op + q * 4) = o;
    }
}

// ---------------------------------------------------------------------------
extern "C" void kernel_launch(void* const* d_in, const int* in_sizes, int n_in,
                              void* d_out, int out_size)
{
    const float* x     = (const float*)d_in[0];
    // d_in[1] = expert_frequency (equal capacities) — unused
    const float* W     = (const float*)d_in[2];
    const float* bias  = (const float*)d_in[3];
    const float* gamma = (const float*)d_in[4];
    const float* beta  = (const float*)d_in[5];
    float*       out   = (float*)d_out;

    __nv_bfloat16 *xhi, *xlo, *whi, *wlo;
    float* h;
    cudaGetSymbolAddress((void**)&xhi, g_xhi);
    cudaGetSymbolAddress((void**)&xlo, g_xlo);
    cudaGetSymbolAddress((void**)&whi, g_whi);
    cudaGetSymbolAddress((void**)&wlo, g_wlo);
    cudaGetSymbolAddress((void**)&h,   g_h);

    static bool attr_done = false;
    if (!attr_done) {
        cudaFuncSetAttribute(gemm_tc_kernel,
                             cudaFuncAttributeMaxDynamicSharedMemorySize, SMEM_SIZE);
        attr_done = true;
    }

    convert_x_kernel<<<NTOK * DIM / (256 * 4), 256>>>(x, xhi, xlo);
    convert_w_kernel<<<dim3(DIM / 32, DIM / 32, NEXP), 256>>>(W, whi, wlo);

    dim3 grid(DIM / 256, CAP / 128, NEXP);  // 4 x 8 x 8 = 256 CTAs
    gemm_tc_kernel<<<grid, 256, SMEM_SIZE>>>(xhi, xlo, whi, wlo, bias, h);

    layernorm_kernel<<<NTOK / 4, 256>>>(h, gamma, beta, out);
}

// round 5
// speedup vs baseline: 1.1482x; 1.1482x over previous
#include <cuda_runtime.h>
#include <cuda_bf16.h>
#include <cstdint>

#define NTOK   8192
#define DIM    1024
#define NEXP   8
#define CAP    1024
#define LN_EPS 1e-5f

// Arch-specific feature gate: tcgen05 only exists on sm_100a/sm_103a targets.
#if defined(__CUDA_ARCH_FEAT_SM103_ALL) || defined(__CUDA_ARCH_FEAT_SM100_ALL)
#define HAS_TCGEN05 1
#else
#define HAS_TCGEN05 0
#endif

// ---------------- scratch (device globals: no allocation) -------------------
__device__ __nv_bfloat16 g_xhi[NTOK * DIM];
__device__ __nv_bfloat16 g_xlo[NTOK * DIM];
__device__ __nv_bfloat16 g_whi[NEXP * DIM * DIM];   // transposed: [e][n][k]
__device__ __nv_bfloat16 g_wlo[NEXP * DIM * DIM];
__device__ float         g_h  [NTOK * DIM];

// ---------------- PTX helpers (guarded) -------------------------------------
#if HAS_TCGEN05
__device__ __forceinline__ uint32_t smem_u32(const void* p) {
    uint32_t a;
    asm("{ .reg .u64 t; cvta.to.shared.u64 t, %1; cvt.u32.u64 %0, t; }" : "=r"(a) : "l"(p));
    return a;
}
__device__ __forceinline__ uint32_t elect_one_pred() {
    uint32_t p;
    asm volatile("{\n\t.reg .pred p;\n\telect.sync _|p, 0xFFFFFFFF;\n\tselp.b32 %0, 1, 0, p;\n\t}" : "=r"(p));
    return p;
}

#define CP_ASYNC16(dst_u32, src_ptr) \
    asm volatile("cp.async.cg.shared.global [%0], [%1], 16;" :: "r"(dst_u32), "l"(src_ptr) : "memory")
#define CP_COMMIT() asm volatile("cp.async.commit_group;" ::: "memory")
#define CP_WAIT0()  asm volatile("cp.async.wait_group 0;" ::: "memory")

#define MBARRIER_INIT(addr, cnt) \
    asm volatile("mbarrier.init.shared.b64 [%0], %1;" :: "r"(addr), "r"(cnt) : "memory")
#define MBARRIER_INVAL(addr) \
    asm volatile("mbarrier.inval.shared.b64 [%0];" :: "r"(addr) : "memory")
#define MBARRIER_WAIT_PARITY(addr, par) do {                                        \
    uint32_t _m = (addr), _p = (par), _d;                                           \
    asm volatile("{\n\t.reg .pred p;\n\t"                                           \
        "mbarrier.try_wait.parity.acquire.cta.shared::cta.b64 p, [%1], %2;\n\t"     \
        "selp.b32 %0, 1, 0, p;\n\t}" : "=r"(_d) : "r"(_m), "r"(_p) : "memory");     \
    if (!_d) {                                                                      \
        asm volatile("{\n\t.reg .pred P1;\n\t"                                      \
            "WL_%=:\n\t"                                                            \
            "mbarrier.try_wait.parity.acquire.cta.shared::cta.b64 P1, [%0], %1, 0x989680;\n\t" \
            "@P1 bra.uni WD_%=;\n\tbra.uni WL_%=;\n\tWD_%=:\n\t}"                   \
            :: "r"(_m), "r"(_p) : "memory");                                        \
    } } while (0)

#define TCGEN05_ALLOC(smem_addr, ncols) \
    asm volatile("tcgen05.alloc.cta_group::1.sync.aligned.shared::cta.b32 [%0], %1;" \
                 :: "r"(smem_addr), "r"(ncols) : "memory")
#define TCGEN05_DEALLOC(tmem, ncols) \
    asm volatile("tcgen05.dealloc.cta_group::1.sync.aligned.b32 %0, %1;" :: "r"(tmem), "r"(ncols))
#define TCGEN05_RELINQ() \
    asm volatile("tcgen05.relinquish_alloc_permit.cta_group::1.sync.aligned;")
#define TCGEN05_COMMIT(mbar) \
    asm volatile("tcgen05.commit.cta_group::1.mbarrier::arrive::one.shared::cluster.b64 [%0];" \
                 :: "r"(mbar) : "memory")
#define TCGEN05_FENCE_AFTER() \
    asm volatile("tcgen05.fence::after_thread_sync;" ::: "memory")
#define TCGEN05_FENCE_BEFORE() \
    asm volatile("tcgen05.fence::before_thread_sync;" ::: "memory")
#define TCGEN05_WAIT_LD() \
    asm volatile("tcgen05.wait::ld.sync.aligned;" ::: "memory")
#define FENCE_PROXY_ASYNC() \
    asm volatile("fence.proxy.async.shared::cta;" ::: "memory")

#define TCGEN05_LD_X32(r, tmem_addr) \
    asm volatile("tcgen05.ld.sync.aligned.32x32b.x32.b32 " \
        "{%0, %1, %2, %3, %4, %5, %6, %7, %8, %9, %10, %11, %12, %13, %14, %15, " \
        " %16, %17, %18, %19, %20, %21, %22, %23, %24, %25, %26, %27, %28, %29, %30, %31}, [%32];" \
        : "=r"((r)[0]),  "=r"((r)[1]),  "=r"((r)[2]),  "=r"((r)[3]),  \
          "=r"((r)[4]),  "=r"((r)[5]),  "=r"((r)[6]),  "=r"((r)[7]),  \
          "=r"((r)[8]),  "=r"((r)[9]),  "=r"((r)[10]), "=r"((r)[11]), \
          "=r"((r)[12]), "=r"((r)[13]), "=r"((r)[14]), "=r"((r)[15]), \
          "=r"((r)[16]), "=r"((r)[17]), "=r"((r)[18]), "=r"((r)[19]), \
          "=r"((r)[20]), "=r"((r)[21]), "=r"((r)[22]), "=r"((r)[23]), \
          "=r"((r)[24]), "=r"((r)[25]), "=r"((r)[26]), "=r"((r)[27]), \
          "=r"((r)[28]), "=r"((r)[29]), "=r"((r)[30]), "=r"((r)[31]) \
        : "r"(tmem_addr))

// SS-mode bf16 MMA, cta_group::1, fp32 accumulate in TMEM
__device__ __forceinline__ void mma_f16_ss(uint32_t d_tmem, uint64_t a_desc,
                                           uint64_t b_desc, uint32_t idesc, bool acc) {
    uint32_t en = acc ? 1u : 0u, z = 0u;
    asm volatile("{\n\t.reg .pred p;\n\tsetp.ne.u32 p, %5, 0;\n\t"
        "tcgen05.mma.cta_group::1.kind::f16 [%0], %1, %2, %3, {%4, %4, %4, %4}, p;\n\t}"
        :: "r"(d_tmem), "l"(a_desc), "l"(b_desc), "r"(idesc), "r"(z), "r"(en) : "memory");
}

// SW128 K-major descriptor (LBO=1, SBO=64, version=1, layout=SW128)
static __device__ __forceinline__ uint64_t make_desc(uint32_t addr) {
    const uint64_t BASE = (2ull << 61) | (1ull << 46) | (64ull << 32) | (1ull << 16);
    return BASE | ((uint64_t)(addr >> 4) & 0x3FFFull);
}

// idesc: F32 out, BF16 in, M=128, N=256
#define MMA_IDESC ((1u << 4) | (1u << 7) | (1u << 10) | ((256u / 8) << 17) | ((128u / 16) << 24))
#endif // HAS_TCGEN05

// ---------------------------------------------------------------------------
// Conversion: X fp32 -> (hi, lo) bf16
// ---------------------------------------------------------------------------
__global__ __launch_bounds__(256)
void convert_x_kernel(const float* __restrict__ X,
                      __nv_bfloat16* __restrict__ Xhi,
                      __nv_bfloat16* __restrict__ Xlo)
{
    int idx = blockIdx.x * 256 + threadIdx.x;       // float4 index
    float4 v = ((const float4*)X)[idx];
    __nv_bfloat16 h[4], l[4];
    float vv[4] = {v.x, v.y, v.z, v.w};
    #pragma unroll
    for (int i = 0; i < 4; ++i) {
        h[i] = __float2bfloat16(vv[i]);
        l[i] = __float2bfloat16(vv[i] - __bfloat162float(h[i]));
    }
    *(uint2*)(Xhi + (size_t)idx * 4) = *(uint2*)h;
    *(uint2*)(Xlo + (size_t)idx * 4) = *(uint2*)l;
}

// ---------------------------------------------------------------------------
// Conversion + transpose: W[e][k][n] fp32 -> Wt(hi/lo)[e][n][k] bf16
// ---------------------------------------------------------------------------
__global__ __launch_bounds__(256)
void convert_w_kernel(const float* __restrict__ W,
                      __nv_bfloat16* __restrict__ Whi,
                      __nv_bfloat16* __restrict__ Wlo)
{
    __shared__ float t[32][33];
    const int e  = blockIdx.z;
    const int k0 = blockIdx.y * 32;
    const int n0 = blockIdx.x * 32;
    const int tx = threadIdx.x & 31;
    const int ty = threadIdx.x >> 5;    // 0..7

    const float* Wp = W + (size_t)e * DIM * DIM;
    #pragma unroll
    for (int r = 0; r < 4; ++r) {
        int k = k0 + ty + 8 * r;
        t[ty + 8 * r][tx] = Wp[(size_t)k * DIM + n0 + tx];
    }
    __syncthreads();
    #pragma unroll
    for (int r = 0; r < 4; ++r) {
        int n = n0 + ty + 8 * r;
        float v = t[tx][ty + 8 * r];
        __nv_bfloat16 h = __float2bfloat16(v);
        __nv_bfloat16 l = __float2bfloat16(v - __bfloat162float(h));
        size_t off = (size_t)e * DIM * DIM + (size_t)n * DIM + k0 + tx;
        Whi[off] = h;
        Wlo[off] = l;
    }
}

// ---------------------------------------------------------------------------
// GEMM: per expert e, H = relu(X_e @ W_e + b_e).
//   sm_103a image: tcgen05, bf16x3 split, M=128 N=256, K-chunk 64.
//   R3 ordering (wait MMA c-2 -> load chunk c -> MMA c); loads via cp.async.
//   family image : fp32 FFMA fallback (correct, slower).
// ---------------------------------------------------------------------------
#define K_CHUNK   64
#define N_CHUNKS  16               // 1024 / 64
#define BUF_BYTES (96 * 1024)      // Ahi 16K + Alo 16K + Bhi 32K + Blo 32K
#define OFF_A_HI  0
#define OFF_A_LO  16384
#define OFF_B_HI  32768
#define OFF_B_LO  65536
#define OFF_BIAS  (2 * BUF_BYTES)           // 196608, 1KB
#define OFF_TPTR  (OFF_BIAS + 1024)
#define OFF_MBAR0 (OFF_TPTR + 16)
#define OFF_MBAR1 (OFF_MBAR0 + 8)
#define SMEM_SIZE (OFF_MBAR1 + 8)

__global__ __launch_bounds__(256, 1)
void gemm_tc_kernel(const __nv_bfloat16* __restrict__ Xhi,
                    const __nv_bfloat16* __restrict__ Xlo,
                    const __nv_bfloat16* __restrict__ Whi,
                    const __nv_bfloat16* __restrict__ Wlo,
                    const float* __restrict__ bias,
                    float* __restrict__ H)
{
#if HAS_TCGEN05
    extern __shared__ __align__(1024) char smem[];
    const uint32_t sbase  = smem_u32(smem);
    const int e      = blockIdx.z;
    const int tile_n = blockIdx.x * 256;
    const int tile_m = blockIdx.y * 128;
    const int tid    = threadIdx.x;
    const int wid    = tid >> 5;
    const int lid    = tid & 31;

    if (wid == 0) {
        TCGEN05_ALLOC(sbase + OFF_TPTR, 256);
        TCGEN05_RELINQ();
    }
    if (tid == 0) {
        MBARRIER_INIT(sbase + OFF_MBAR0, 1);
        MBARRIER_INIT(sbase + OFF_MBAR1, 1);
    }
    ((float*)(smem + OFF_BIAS))[tid] = bias[e * DIM + tile_n + tid];
    __syncthreads();
    uint32_t tmem;
    asm volatile("ld.shared.b32 %0, [%1];" : "=r"(tmem) : "r"(sbase + OFF_TPTR));

    const __nv_bfloat16* Ah = Xhi + (size_t)(e * CAP + tile_m) * DIM;
    const __nv_bfloat16* Al = Xlo + (size_t)(e * CAP + tile_m) * DIM;
    const __nv_bfloat16* Bh = Whi + ((size_t)e * DIM + tile_n) * DIM;
    const __nv_bfloat16* Bl = Wlo + ((size_t)e * DIM + tile_n) * DIM;

    // per-thread cp.async slices: A rows 2 threads/row (4 granules each), B 1 row/thread
    const int rA  = tid >> 1;
    const int cA0 = (tid & 1) * 4;
    const int rB  = tid;

    for (int c = 0; c < N_CHUNKS; ++c) {
        if (c >= 2) {
            // buffer c&1 was last read by MMA chunk c-2 (commit #(c>>1)-1 on this mbar)
            uint32_t mb = sbase + ((c & 1) ? OFF_MBAR1 : OFF_MBAR0);
            MBARRIER_WAIT_PARITY(mb, ((c >> 1) - 1) & 1);
        }
        const uint32_t bb = sbase + (c & 1) * BUF_BYTES;
        const int k0 = c * K_CHUNK;

        #pragma unroll
        for (int i = 0; i < 4; ++i) {
            int cg = cA0 + i;
            int sw = rA * 128 + ((cg ^ (rA & 7)) << 4);
            CP_ASYNC16(bb + OFF_A_HI + sw, (const char*)(Ah + (size_t)rA * DIM + k0) + cg * 16);
            CP_ASYNC16(bb + OFF_A_LO + sw, (const char*)(Al + (size_t)rA * DIM + k0) + cg * 16);
        }
        #pragma unroll
        for (int cg = 0; cg < 8; ++cg) {
            int sw = rB * 128 + ((cg ^ (rB & 7)) << 4);
            CP_ASYNC16(bb + OFF_B_HI + sw, (const char*)(Bh + (size_t)rB * DIM + k0) + cg * 16);
            CP_ASYNC16(bb + OFF_B_LO + sw, (const char*)(Bl + (size_t)rB * DIM + k0) + cg * 16);
        }
        CP_COMMIT();
        CP_WAIT0();
        __syncthreads();                         // chunk c resident; MMA c-1 still in flight

        if (wid == 0 && elect_one_pred()) {
            FENCE_PROXY_ASYNC();
            uint64_t dAh = make_desc(bb + OFF_A_HI);
            uint64_t dAl = make_desc(bb + OFF_A_LO);
            uint64_t dBh = make_desc(bb + OFF_B_HI);
            uint64_t dBl = make_desc(bb + OFF_B_LO);
            #pragma unroll
            for (int kk = 0; kk < 4; ++kk) {     // K=16 steps (+2 units = 32B)
                mma_f16_ss(tmem, dAh + kk * 2, dBh + kk * 2, MMA_IDESC, !(c == 0 && kk == 0));
                mma_f16_ss(tmem, dAh + kk * 2, dBl + kk * 2, MMA_IDESC, true);
                mma_f16_ss(tmem, dAl + kk * 2, dBh + kk * 2, MMA_IDESC, true);
            }
            TCGEN05_COMMIT(sbase + ((c & 1) ? OFF_MBAR1 : OFF_MBAR0));
        }
    }

    // drain: 8 commits on each mbar; final completed phase = 7 (parity 1)
    MBARRIER_WAIT_PARITY(sbase + OFF_MBAR0, 1);
    MBARRIER_WAIT_PARITY(sbase + OFF_MBAR1, 1);
    TCGEN05_FENCE_AFTER();

    // epilogue: warps 0-3 read TMEM (32-lane subpartition = 32 M rows each)
    if (wid < 4) {
        const int row = tile_m + wid * 32 + lid;
        float* outp = H + (size_t)(e * CAP + row) * DIM + tile_n;
        const float* bs = (const float*)(smem + OFF_BIAS);
        #pragma unroll
        for (int base = 0; base < 256; base += 32) {
            uint32_t r[32];
            TCGEN05_LD_X32(r, tmem + base);
            TCGEN05_WAIT_LD();
            float v[32];
            #pragma unroll
            for (int i = 0; i < 32; ++i)
                v[i] = fmaxf(__uint_as_float(r[i]) + bs[base + i], 0.f);
            #pragma unroll
            for (int q = 0; q < 8; ++q)
                *(float4*)(outp + base + q * 4) = *(float4*)&v[q * 4];
        }
        TCGEN05_FENCE_BEFORE();
    }
    __syncthreads();
    if (tid == 0) { MBARRIER_INVAL(sbase + OFF_MBAR0); MBARRIER_INVAL(sbase + OFF_MBAR1); }
    __syncthreads();
    if (wid == 0) TCGEN05_DEALLOC(tmem, 256);

#else
    // ---------------- fp32 FFMA fallback (family-level image) ----------------
    extern __shared__ __align__(1024) char smem_raw[];
    float* As = (float*)smem_raw;                  // [16][128]
    float* Bs = (float*)(smem_raw + 16 * 128 * 4); // [16][256]

    const int e      = blockIdx.z;
    const int tile_n = blockIdx.x * 256;
    const int tile_m = blockIdx.y * 128;
    const int tid    = threadIdx.x;
    const int tx     = tid & 15;     // n: 16 cols each
    const int ty     = tid >> 4;     // m: 8 rows each

    const __nv_bfloat16* Ah = Xhi + (size_t)(e * CAP + tile_m) * DIM;
    const __nv_bfloat16* Al = Xlo + (size_t)(e * CAP + tile_m) * DIM;
    const __nv_bfloat16* Bh = Whi + ((size_t)e * DIM + tile_n) * DIM;
    const __nv_bfloat16* Bl = Wlo + ((size_t)e * DIM + tile_n) * DIM;

    float acc[8][16];
    #pragma unroll
    for (int i = 0; i < 8; ++i)
        #pragma unroll
        for (int j = 0; j < 16; ++j) acc[i][j] = 0.f;

    for (int k0 = 0; k0 < DIM; k0 += 16) {
        #pragma unroll
        for (int it = 0; it < 8; ++it) {          // A: 128x16
            int g = tid + it * 256;
            int r = g >> 4, kc = g & 15;
            As[kc * 128 + r] = __bfloat162float(Ah[(size_t)r * DIM + k0 + kc]) +
                               __bfloat162float(Al[(size_t)r * DIM + k0 + kc]);
        }
        #pragma unroll
        for (int it = 0; it < 16; ++it) {         // B: 256(n) x16(k)
            int g = tid + it * 256;
            int n = g >> 4, kc = g & 15;
            Bs[kc * 256 + n] = __bfloat162float(Bh[(size_t)n * DIM + k0 + kc]) +
                               __bfloat162float(Bl[(size_t)n * DIM + k0 + kc]);
        }
        __syncthreads();
        #pragma unroll
        for (int kc = 0; kc < 16; ++kc) {
            float a[8], b[16];
            #pragma unroll
            for (int i = 0; i < 8; ++i)  a[i] = As[kc * 128 + ty * 8 + i];
            #pragma unroll
            for (int j = 0; j < 16; ++j) b[j] = Bs[kc * 256 + tx * 16 + j];
            #pragma unroll
            for (int i = 0; i < 8; ++i)
                #pragma unroll
                for (int j = 0; j < 16; ++j)
                    acc[i][j] = fmaf(a[i], b[j], acc[i][j]);
        }
        __syncthreads();
    }

    #pragma unroll
    for (int i = 0; i < 8; ++i) {
        int row = tile_m + ty * 8 + i;
        float* outp = H + (size_t)(e * CAP + row) * DIM + tile_n + tx * 16;
        #pragma unroll
        for (int j = 0; j < 16; ++j) {
            float bv = bias[e * DIM + tile_n + tx * 16 + j];
            outp[j] = fmaxf(acc[i][j] + bv, 0.f);
        }
    }
#endif
}

// ---------------------------------------------------------------------------
// LayerNorm over D=1024 per row; one 256-thread CTA per token. (R3 version)
// ---------------------------------------------------------------------------
__global__ __launch_bounds__(256)
void layernorm_kernel(const float* __restrict__ H,
                      const float* __restrict__ gamma,
                      const float* __restrict__ beta,
                      float* __restrict__ out)
{
    const int row = blockIdx.x;
    const int e   = row >> 10;
    const int tid = threadIdx.x;

    const float* h = H + (size_t)row * DIM;
    float4 v = *(const float4*)(h + tid * 4);

    float s  = v.x + v.y + v.z + v.w;
    float sq = v.x * v.x + v.y * v.y + v.z * v.z + v.w * v.w;

    #pragma unroll
    for (int off = 16; off > 0; off >>= 1) {
        s  += __shfl_xor_sync(0xffffffffu, s,  off);
        sq += __shfl_xor_sync(0xffffffffu, sq, off);
    }

    __shared__ float red_s[8], red_q[8];
    const int wid = tid >> 5, lid = tid & 31;
    if (lid == 0) { red_s[wid] = s; red_q[wid] = sq; }
    __syncthreads();

    __shared__ float s_mean, s_rstd;
    if (wid == 0) {
        float ts = (lid < 8) ? red_s[lid] : 0.f;
        float tq = (lid < 8) ? red_q[lid] : 0.f;
        #pragma unroll
        for (int off = 4; off > 0; off >>= 1) {
            ts += __shfl_xor_sync(0xffffffffu, ts, off);
            tq += __shfl_xor_sync(0xffffffffu, tq, off);
        }
        if (lid == 0) {
            float mean = ts * (1.f / DIM);
            float var  = tq * (1.f / DIM) - mean * mean;
            s_mean = mean;
            s_rstd = rsqrtf(var + LN_EPS);
        }
    }
    __syncthreads();

    const float mean = s_mean, rstd = s_rstd;
    float4 g  = *(const float4*)(gamma + (size_t)e * DIM + tid * 4);
    float4 bt = *(const float4*)(beta  + (size_t)e * DIM + tid * 4);

    float4 o;
    o.x = (v.x - mean) * rstd * g.x + bt.x;
    o.y = (v.y - mean) * rstd * g.y + bt.y;
    o.z = (v.z - mean) * rstd * g.z + bt.z;
    o.w = (v.w - mean) * rstd * g.w + bt.w;
    *(float4*)(out + (size_t)row * DIM + tid * 4) = o;
}

// ---------------------------------------------------------------------------
extern "C" void kernel_launch(void* const* d_in, const int* in_sizes, int n_in,
                              void* d_out, int out_size)
{
    const float* x     = (const float*)d_in[0];
    // d_in[1] = expert_frequency (equal capacities) — unused
    const float* W     = (const float*)d_in[2];
    const float* bias  = (const float*)d_in[3];
    const float* gamma = (const float*)d_in[4];
    const float* beta  = (const float*)d_in[5];
    float*       out   = (float*)d_out;

    __nv_bfloat16 *xhi, *xlo, *whi, *wlo;
    float* h;
    cudaGetSymbolAddress((void**)&xhi, g_xhi);
    cudaGetSymbolAddress((void**)&xlo, g_xlo);
    cudaGetSymbolAddress((void**)&whi, g_whi);
    cudaGetSymbolAddress((void**)&wlo, g_wlo);
    cudaGetSymbolAddress((void**)&h,   g_h);

    static bool attr_done = false;
    if (!attr_done) {
        cudaFuncSetAttribute(gemm_tc_kernel,
                             cudaFuncAttributeMaxDynamicSharedMemorySize, SMEM_SIZE);
        attr_done = true;
    }

    convert_x_kernel<<<NTOK * DIM / (256 * 4), 256>>>(x, xhi, xlo);
    convert_w_kernel<<<dim3(DIM / 32, DIM / 32, NEXP), 256>>>(W, whi, wlo);

    dim3 grid(DIM / 256, CAP / 128, NEXP);  // 4 x 8 x 8 = 256 CTAs
    gemm_tc_kernel<<<grid, 256, SMEM_SIZE>>>(xhi, xlo, whi, wlo, bias, h);

    layernorm_kernel<<<NTOK, 256>>>(h, gamma, beta, out);
}

// round 6
// speedup vs baseline: 1.4005x; 1.2198x over previous
#include <cuda_runtime.h>
#include <cuda_bf16.h>
#include <cstdint>

#define NTOK   8192
#define DIM    1024
#define NEXP   8
#define CAP    1024
#define LN_EPS 1e-5f

// Arch-specific feature gate: tcgen05 only exists on sm_100a/sm_103a targets.
#if defined(__CUDA_ARCH_FEAT_SM103_ALL) || defined(__CUDA_ARCH_FEAT_SM100_ALL)
#define HAS_TCGEN05 1
#else
#define HAS_TCGEN05 0
#endif

// ---------------- scratch (device globals: no allocation) -------------------
__device__ __nv_bfloat16 g_xhi[NTOK * DIM];
__device__ __nv_bfloat16 g_xlo[NTOK * DIM];
__device__ __nv_bfloat16 g_whi[NEXP * DIM * DIM];   // transposed: [e][n][k]
__device__ __nv_bfloat16 g_wlo[NEXP * DIM * DIM];
__device__ float         g_h  [NTOK * DIM];

// ---------------- PTX helpers (guarded) -------------------------------------
#if HAS_TCGEN05
__device__ __forceinline__ uint32_t smem_u32(const void* p) {
    uint32_t a;
    asm("{ .reg .u64 t; cvta.to.shared.u64 t, %1; cvt.u32.u64 %0, t; }" : "=r"(a) : "l"(p));
    return a;
}
__device__ __forceinline__ uint32_t elect_one_pred() {
    uint32_t p;
    asm volatile("{\n\t.reg .pred p;\n\telect.sync _|p, 0xFFFFFFFF;\n\tselp.b32 %0, 1, 0, p;\n\t}" : "=r"(p));
    return p;
}

#define CP_ASYNC16(dst_u32, src_ptr) \
    asm volatile("cp.async.cg.shared.global [%0], [%1], 16;" :: "r"(dst_u32), "l"(src_ptr) : "memory")
#define CP_ASYNC_MBAR_ARRIVE(mbar) \
    asm volatile("cp.async.mbarrier.arrive.noinc.shared.b64 [%0];" :: "r"(mbar) : "memory")

#define MBARRIER_INIT(addr, cnt) \
    asm volatile("mbarrier.init.shared.b64 [%0], %1;" :: "r"(addr), "r"(cnt) : "memory")
#define MBARRIER_INVAL(addr) \
    asm volatile("mbarrier.inval.shared.b64 [%0];" :: "r"(addr) : "memory")
#define MBARRIER_WAIT_PARITY(addr, par) do {                                        \
    uint32_t _m = (addr), _p = (par), _d;                                           \
    asm volatile("{\n\t.reg .pred p;\n\t"                                           \
        "mbarrier.try_wait.parity.acquire.cta.shared::cta.b64 p, [%1], %2;\n\t"     \
        "selp.b32 %0, 1, 0, p;\n\t}" : "=r"(_d) : "r"(_m), "r"(_p) : "memory");     \
    if (!_d) {                                                                      \
        asm volatile("{\n\t.reg .pred P1;\n\t"                                      \
            "WL_%=:\n\t"                                                            \
            "mbarrier.try_wait.parity.acquire.cta.shared::cta.b64 P1, [%0], %1, 0x989680;\n\t" \
            "@P1 bra.uni WD_%=;\n\tbra.uni WL_%=;\n\tWD_%=:\n\t}"                   \
            :: "r"(_m), "r"(_p) : "memory");                                        \
    } } while (0)

#define TCGEN05_ALLOC(smem_addr, ncols) \
    asm volatile("tcgen05.alloc.cta_group::1.sync.aligned.shared::cta.b32 [%0], %1;" \
                 :: "r"(smem_addr), "r"(ncols) : "memory")
#define TCGEN05_DEALLOC(tmem, ncols) \
    asm volatile("tcgen05.dealloc.cta_group::1.sync.aligned.b32 %0, %1;" :: "r"(tmem), "r"(ncols))
#define TCGEN05_RELINQ() \
    asm volatile("tcgen05.relinquish_alloc_permit.cta_group::1.sync.aligned;")
#define TCGEN05_COMMIT(mbar) \
    asm volatile("tcgen05.commit.cta_group::1.mbarrier::arrive::one.shared::cluster.b64 [%0];" \
                 :: "r"(mbar) : "memory")
#define TCGEN05_FENCE_AFTER() \
    asm volatile("tcgen05.fence::after_thread_sync;" ::: "memory")
#define TCGEN05_FENCE_BEFORE() \
    asm volatile("tcgen05.fence::before_thread_sync;" ::: "memory")
#define TCGEN05_WAIT_LD() \
    asm volatile("tcgen05.wait::ld.sync.aligned;" ::: "memory")
#define FENCE_PROXY_ASYNC() \
    asm volatile("fence.proxy.async.shared::cta;" ::: "memory")

#define TCGEN05_LD_X32(r, tmem_addr) \
    asm volatile("tcgen05.ld.sync.aligned.32x32b.x32.b32 " \
        "{%0, %1, %2, %3, %4, %5, %6, %7, %8, %9, %10, %11, %12, %13, %14, %15, " \
        " %16, %17, %18, %19, %20, %21, %22, %23, %24, %25, %26, %27, %28, %29, %30, %31}, [%32];" \
        : "=r"((r)[0]),  "=r"((r)[1]),  "=r"((r)[2]),  "=r"((r)[3]),  \
          "=r"((r)[4]),  "=r"((r)[5]),  "=r"((r)[6]),  "=r"((r)[7]),  \
          "=r"((r)[8]),  "=r"((r)[9]),  "=r"((r)[10]), "=r"((r)[11]), \
          "=r"((r)[12]), "=r"((r)[13]), "=r"((r)[14]), "=r"((r)[15]), \
          "=r"((r)[16]), "=r"((r)[17]), "=r"((r)[18]), "=r"((r)[19]), \
          "=r"((r)[20]), "=r"((r)[21]), "=r"((r)[22]), "=r"((r)[23]), \
          "=r"((r)[24]), "=r"((r)[25]), "=r"((r)[26]), "=r"((r)[27]), \
          "=r"((r)[28]), "=r"((r)[29]), "=r"((r)[30]), "=r"((r)[31]) \
        : "r"(tmem_addr))

// SS-mode bf16 MMA, cta_group::1, fp32 accumulate in TMEM
__device__ __forceinline__ void mma_f16_ss(uint32_t d_tmem, uint64_t a_desc,
                                           uint64_t b_desc, uint32_t idesc, bool acc) {
    uint32_t en = acc ? 1u : 0u, z = 0u;
    asm volatile("{\n\t.reg .pred p;\n\tsetp.ne.u32 p, %5, 0;\n\t"
        "tcgen05.mma.cta_group::1.kind::f16 [%0], %1, %2, %3, {%4, %4, %4, %4}, p;\n\t}"
        :: "r"(d_tmem), "l"(a_desc), "l"(b_desc), "r"(idesc), "r"(z), "r"(en) : "memory");
}

// SW64 K-major descriptor: layout=4 (SW64), version=1, SBO=32 (512B = 8 rows x 64B), LBO=1
static __device__ __forceinline__ uint64_t make_desc_sw64(uint32_t addr) {
    const uint64_t BASE = (4ull << 61) | (1ull << 46) | (32ull << 32) | (1ull << 16);
    return BASE | ((uint64_t)(addr >> 4) & 0x3FFFull);
}

// idesc: F32 out, BF16 in, M=128, N=256
#define MMA_IDESC ((1u << 4) | (1u << 7) | (1u << 10) | ((256u / 8) << 17) | ((128u / 16) << 24))
#endif // HAS_TCGEN05

// ---------------------------------------------------------------------------
// Conversion: X fp32 -> (hi, lo) bf16
// ---------------------------------------------------------------------------
__global__ __launch_bounds__(256)
void convert_x_kernel(const float* __restrict__ X,
                      __nv_bfloat16* __restrict__ Xhi,
                      __nv_bfloat16* __restrict__ Xlo)
{
    int idx = blockIdx.x * 256 + threadIdx.x;       // float4 index
    float4 v = ((const float4*)X)[idx];
    __nv_bfloat16 h[4], l[4];
    float vv[4] = {v.x, v.y, v.z, v.w};
    #pragma unroll
    for (int i = 0; i < 4; ++i) {
        h[i] = __float2bfloat16(vv[i]);
        l[i] = __float2bfloat16(vv[i] - __bfloat162float(h[i]));
    }
    *(uint2*)(Xhi + (size_t)idx * 4) = *(uint2*)h;
    *(uint2*)(Xlo + (size_t)idx * 4) = *(uint2*)l;
}

// ---------------------------------------------------------------------------
// Conversion + transpose: W[e][k][n] fp32 -> Wt(hi/lo)[e][n][k] bf16
// ---------------------------------------------------------------------------
__global__ __launch_bounds__(256)
void convert_w_kernel(const float* __restrict__ W,
                      __nv_bfloat16* __restrict__ Whi,
                      __nv_bfloat16* __restrict__ Wlo)
{
    __shared__ float t[32][33];
    const int e  = blockIdx.z;
    const int k0 = blockIdx.y * 32;
    const int n0 = blockIdx.x * 32;
    const int tx = threadIdx.x & 31;
    const int ty = threadIdx.x >> 5;    // 0..7

    const float* Wp = W + (size_t)e * DIM * DIM;
    #pragma unroll
    for (int r = 0; r < 4; ++r) {
        int k = k0 + ty + 8 * r;
        t[ty + 8 * r][tx] = Wp[(size_t)k * DIM + n0 + tx];
    }
    __syncthreads();
    #pragma unroll
    for (int r = 0; r < 4; ++r) {
        int n = n0 + ty + 8 * r;
        float v = t[tx][ty + 8 * r];
        __nv_bfloat16 h = __float2bfloat16(v);
        __nv_bfloat16 l = __float2bfloat16(v - __bfloat162float(h));
        size_t off = (size_t)e * DIM * DIM + (size_t)n * DIM + k0 + tx;
        Whi[off] = h;
        Wlo[off] = l;
    }
}

// ---------------------------------------------------------------------------
// GEMM: per expert e, H = relu(X_e @ W_e + b_e), bf16x3 split.
//   sm_103a: warp-specialized pipeline. Tile M=256 N=256, K_CHUNK=32, 3 stages.
//   Warps 0-3 producers (cp.async -> full mbar), warp 4 MMA (commit -> empty).
//   family image: trivial correct fallback (never selected on GB300).
// ---------------------------------------------------------------------------
#define NSTAGE      3
#define K_CHUNK     32
#define N_CHUNKS    32               // 1024 / 32
#define STAGE_BYTES 65536            // Ahi16K Alo16K Bhi16K Blo16K (256 rows x 64B each)
#define T_A_HI  0
#define T_A_LO  16384
#define T_B_HI  32768
#define T_B_LO  49152
#define OFF_BIAS  (NSTAGE * STAGE_BYTES)       // 196608, 1KB
#define OFF_TPTR  (OFF_BIAS + 1024)
#define OFF_FULL  (OFF_TPTR + 16)              // 3 x 8B
#define OFF_EMPTY (OFF_FULL + 24)              // 3 x 8B
#define OFF_FINAL (OFF_EMPTY + 24)
#define SMEM_SIZE (OFF_FINAL + 8)

__global__ __launch_bounds__(256, 1)
void gemm_tc_kernel(const __nv_bfloat16* __restrict__ Xhi,
                    const __nv_bfloat16* __restrict__ Xlo,
                    const __nv_bfloat16* __restrict__ Whi,
                    const __nv_bfloat16* __restrict__ Wlo,
                    const float* __restrict__ bias,
                    float* __restrict__ H)
{
#if HAS_TCGEN05
    extern __shared__ __align__(1024) char smem[];
    const uint32_t sbase  = smem_u32(smem);
    const int e      = blockIdx.z;
    const int tile_n = blockIdx.x * 256;
    const int tile_m = blockIdx.y * 256;
    const int tid    = threadIdx.x;
    const int wid    = tid >> 5;
    const int lid    = tid & 31;

    if (wid == 0) {
        TCGEN05_ALLOC(sbase + OFF_TPTR, 512);
        TCGEN05_RELINQ();
    }
    if (tid == 0) {
        #pragma unroll
        for (int s = 0; s < NSTAGE; ++s) {
            MBARRIER_INIT(sbase + OFF_FULL  + s * 8, 128);  // 128 producer threads
            MBARRIER_INIT(sbase + OFF_EMPTY + s * 8, 1);    // one tcgen05.commit
        }
        MBARRIER_INIT(sbase + OFF_FINAL, 1);
    }
    ((float*)(smem + OFF_BIAS))[tid] = bias[e * DIM + tile_n + tid];
    __syncthreads();
    uint32_t tmem;
    asm volatile("ld.shared.b32 %0, [%1];" : "=r"(tmem) : "r"(sbase + OFF_TPTR));

    const __nv_bfloat16* Ah = Xhi + (size_t)(e * CAP + tile_m) * DIM;
    const __nv_bfloat16* Al = Xlo + (size_t)(e * CAP + tile_m) * DIM;
    const __nv_bfloat16* Bh = Whi + ((size_t)e * DIM + tile_n) * DIM;
    const __nv_bfloat16* Bl = Wlo + ((size_t)e * DIM + tile_n) * DIM;

    if (wid < 4) {
        // ---------------- producers: 128 threads, 2 rows each, 4 granules/row/tensor
        const int r0 = tid * 2;
        int st = 0, it = 0;
        for (int c = 0; c < N_CHUNKS; ++c) {
            if (c >= NSTAGE)
                MBARRIER_WAIT_PARITY(sbase + OFF_EMPTY + st * 8, (it - 1) & 1);
            const uint32_t bb = sbase + st * STAGE_BYTES;
            const size_t koff = (size_t)(c * K_CHUNK);      // element offset in row
            #pragma unroll
            for (int rr = 0; rr < 2; ++rr) {
                const int r = r0 + rr;
                const char* pAh = (const char*)(Ah + (size_t)r * DIM + koff);
                const char* pAl = (const char*)(Al + (size_t)r * DIM + koff);
                const char* pBh = (const char*)(Bh + (size_t)r * DIM + koff);
                const char* pBl = (const char*)(Bl + (size_t)r * DIM + koff);
                #pragma unroll
                for (int cg = 0; cg < 4; ++cg) {
                    int byte = r * 64 + cg * 16;
                    int sw   = byte ^ ((byte >> 3) & 0x30);   // SW64 swizzle
                    CP_ASYNC16(bb + T_A_HI + sw, pAh + cg * 16);
                    CP_ASYNC16(bb + T_A_LO + sw, pAl + cg * 16);
                    CP_ASYNC16(bb + T_B_HI + sw, pBh + cg * 16);
                    CP_ASYNC16(bb + T_B_LO + sw, pBl + cg * 16);
                }
            }
            CP_ASYNC_MBAR_ARRIVE(sbase + OFF_FULL + st * 8);
            if (++st == NSTAGE) { st = 0; ++it; }
        }
    } else if (wid == 4) {
        // ---------------- MMA warp (single elected thread)
        if (elect_one_pred()) {
            int st = 0, it = 0;
            for (int c = 0; c < N_CHUNKS; ++c) {
                MBARRIER_WAIT_PARITY(sbase + OFF_FULL + st * 8, it & 1);
                FENCE_PROXY_ASYNC();
                const uint32_t bb = sbase + st * STAGE_BYTES;
                uint64_t dAh = make_desc_sw64(bb + T_A_HI);
                uint64_t dAl = make_desc_sw64(bb + T_A_LO);
                uint64_t dBh = make_desc_sw64(bb + T_B_HI);
                uint64_t dBl = make_desc_sw64(bb + T_B_LO);
                #pragma unroll
                for (int h = 0; h < 2; ++h) {
                    const uint32_t D   = tmem + h * 256;
                    const uint64_t hof = h * 512;             // 128 rows x 64B = 8192B = 512 units
                    #pragma unroll
                    for (int kk = 0; kk < 2; ++kk) {
                        mma_f16_ss(D, dAh + hof + kk * 2, dBh + kk * 2, MMA_IDESC,
                                   !(c == 0 && kk == 0));
                        mma_f16_ss(D, dAh + hof + kk * 2, dBl + kk * 2, MMA_IDESC, true);
                        mma_f16_ss(D, dAl + hof + kk * 2, dBh + kk * 2, MMA_IDESC, true);
                    }
                }
                TCGEN05_COMMIT(sbase + OFF_EMPTY + st * 8);
                if (++st == NSTAGE) { st = 0; ++it; }
            }
            TCGEN05_COMMIT(sbase + OFF_FINAL);
        }
    }

    // ---------------- epilogue: all 8 warps after final MMA completes
    MBARRIER_WAIT_PARITY(sbase + OFF_FINAL, 0);
    TCGEN05_FENCE_AFTER();

    {
        const int half = wid >> 2, sub = wid & 3;
        const int row  = tile_m + half * 128 + sub * 32 + lid;
        float* outp = H + (size_t)(e * CAP + row) * DIM + tile_n;
        const float* bs = (const float*)(smem + OFF_BIAS);
        const uint32_t dbase = tmem + half * 256;
        #pragma unroll
        for (int base = 0; base < 256; base += 32) {
            uint32_t r[32];
            TCGEN05_LD_X32(r, dbase + base);
            TCGEN05_WAIT_LD();
            float v[32];
            #pragma unroll
            for (int i = 0; i < 32; ++i)
                v[i] = fmaxf(__uint_as_float(r[i]) + bs[base + i], 0.f);
            #pragma unroll
            for (int q = 0; q < 8; ++q)
                *(float4*)(outp + base + q * 4) = *(float4*)&v[q * 4];
        }
        TCGEN05_FENCE_BEFORE();
    }
    __syncthreads();
    if (tid == 0) {
        #pragma unroll
        for (int s = 0; s < NSTAGE; ++s) {
            MBARRIER_INVAL(sbase + OFF_FULL  + s * 8);
            MBARRIER_INVAL(sbase + OFF_EMPTY + s * 8);
        }
        MBARRIER_INVAL(sbase + OFF_FINAL);
    }
    __syncthreads();
    if (wid == 0) TCGEN05_DEALLOC(tmem, 512);

#else
    // ---------------- trivial correct fallback (family-level image; not used on GB300)
    const int e      = blockIdx.z;
    const int tile_n = blockIdx.x * 256;
    const int tile_m = blockIdx.y * 256;
    const int tid    = threadIdx.x;
    const int row    = tile_m + tid;
    const __nv_bfloat16* Ahp = Xhi + (size_t)(e * CAP + row) * DIM;
    const __nv_bfloat16* Alp = Xlo + (size_t)(e * CAP + row) * DIM;
    for (int n = 0; n < 256; ++n) {
        const __nv_bfloat16* Bhp = Whi + ((size_t)e * DIM + tile_n + n) * DIM;
        const __nv_bfloat16* Blp = Wlo + ((size_t)e * DIM + tile_n + n) * DIM;
        float s = 0.f;
        for (int k = 0; k < DIM; ++k) {
            float a = __bfloat162float(Ahp[k]) + __bfloat162float(Alp[k]);
            float b = __bfloat162float(Bhp[k]) + __bfloat162float(Blp[k]);
            s = fmaf(a, b, s);
        }
        s += bias[e * DIM + tile_n + n];
        H[(size_t)(e * CAP + row) * DIM + tile_n + n] = fmaxf(s, 0.f);
    }
#endif
}

// ---------------------------------------------------------------------------
// LayerNorm over D=1024 per row; one 256-thread CTA per token. (R3 version)
// ---------------------------------------------------------------------------
__global__ __launch_bounds__(256)
void layernorm_kernel(const float* __restrict__ H,
                      const float* __restrict__ gamma,
                      const float* __restrict__ beta,
                      float* __restrict__ out)
{
    const int row = blockIdx.x;
    const int e   = row >> 10;
    const int tid = threadIdx.x;

    const float* h = H + (size_t)row * DIM;
    float4 v = *(const float4*)(h + tid * 4);

    float s  = v.x + v.y + v.z + v.w;
    float sq = v.x * v.x + v.y * v.y + v.z * v.z + v.w * v.w;

    #pragma unroll
    for (int off = 16; off > 0; off >>= 1) {
        s  += __shfl_xor_sync(0xffffffffu, s,  off);
        sq += __shfl_xor_sync(0xffffffffu, sq, off);
    }

    __shared__ float red_s[8], red_q[8];
    const int wid = tid >> 5, lid = tid & 31;
    if (lid == 0) { red_s[wid] = s; red_q[wid] = sq; }
    __syncthreads();

    __shared__ float s_mean, s_rstd;
    if (wid == 0) {
        float ts = (lid < 8) ? red_s[lid] : 0.f;
        float tq = (lid < 8) ? red_q[lid] : 0.f;
        #pragma unroll
        for (int off = 4; off > 0; off >>= 1) {
            ts += __shfl_xor_sync(0xffffffffu, ts, off);
            tq += __shfl_xor_sync(0xffffffffu, tq, off);
        }
        if (lid == 0) {
            float mean = ts * (1.f / DIM);
            float var  = tq * (1.f / DIM) - mean * mean;
            s_mean = mean;
            s_rstd = rsqrtf(var + LN_EPS);
        }
    }
    __syncthreads();

    const float mean = s_mean, rstd = s_rstd;
    float4 g  = *(const float4*)(gamma + (size_t)e * DIM + tid * 4);
    float4 bt = *(const float4*)(beta  + (size_t)e * DIM + tid * 4);

    float4 o;
    o.x = (v.x - mean) * rstd * g.x + bt.x;
    o.y = (v.y - mean) * rstd * g.y + bt.y;
    o.z = (v.z - mean) * rstd * g.z + bt.z;
    o.w = (v.w - mean) * rstd * g.w + bt.w;
    *(float4*)(out + (size_t)row * DIM + tid * 4) = o;
}

// ---------------------------------------------------------------------------
extern "C" void kernel_launch(void* const* d_in, const int* in_sizes, int n_in,
                              void* d_out, int out_size)
{
    const float* x     = (const float*)d_in[0];
    // d_in[1] = expert_frequency (equal capacities) — unused
    const float* W     = (const float*)d_in[2];
    const float* bias  = (const float*)d_in[3];
    const float* gamma = (const float*)d_in[4];
    const float* beta  = (const float*)d_in[5];
    float*       out   = (float*)d_out;

    __nv_bfloat16 *xhi, *xlo, *whi, *wlo;
    float* h;
    cudaGetSymbolAddress((void**)&xhi, g_xhi);
    cudaGetSymbolAddress((void**)&xlo, g_xlo);
    cudaGetSymbolAddress((void**)&whi, g_whi);
    cudaGetSymbolAddress((void**)&wlo, g_wlo);
    cudaGetSymbolAddress((void**)&h,   g_h);

    static bool attr_done = false;
    if (!attr_done) {
        cudaFuncSetAttribute(gemm_tc_kernel,
                             cudaFuncAttributeMaxDynamicSharedMemorySize, SMEM_SIZE);
        attr_done = true;
    }

    convert_x_kernel<<<NTOK * DIM / (256 * 4), 256>>>(x, xhi, xlo);
    convert_w_kernel<<<dim3(DIM / 32, DIM / 32, NEXP), 256>>>(W, whi, wlo);

    dim3 grid(DIM / 256, CAP / 256, NEXP);  // 4 x 4 x 8 = 128 CTAs (one wave)
    gemm_tc_kernel<<<grid, 256, SMEM_SIZE>>>(xhi, xlo, whi, wlo, bias, h);

    layernorm_kernel<<<NTOK, 256>>>(h, gamma, beta, out);
}

// round 7
// speedup vs baseline: 2.0997x; 1.4992x over previous
#include <cuda_runtime.h>
#include <cuda_bf16.h>
#include <cstdint>

#define NTOK   8192
#define DIM    1024
#define NEXP   8
#define CAP    1024
#define LN_EPS 1e-5f

// Arch-specific feature gate: tcgen05 only exists on sm_100a/sm_103a targets.
#if defined(__CUDA_ARCH_FEAT_SM103_ALL) || defined(__CUDA_ARCH_FEAT_SM100_ALL)
#define HAS_TCGEN05 1
#else
#define HAS_TCGEN05 0
#endif

// ---------------- scratch (device globals: no allocation) -------------------
__device__ __nv_bfloat16 g_xhi[NTOK * DIM];
__device__ __nv_bfloat16 g_xlo[NTOK * DIM];
__device__ __nv_bfloat16 g_whi[NEXP * DIM * DIM];   // transposed: [e][n][k]
__device__ __nv_bfloat16 g_wlo[NEXP * DIM * DIM];
__device__ float         g_h  [NTOK * DIM];

// ---------------- PTX helpers (guarded) -------------------------------------
#if HAS_TCGEN05
__device__ __forceinline__ uint32_t smem_u32(const void* p) {
    uint32_t a;
    asm("{ .reg .u64 t; cvta.to.shared.u64 t, %1; cvt.u32.u64 %0, t; }" : "=r"(a) : "l"(p));
    return a;
}
__device__ __forceinline__ uint32_t elect_one_pred() {
    uint32_t p;
    asm volatile("{\n\t.reg .pred p;\n\telect.sync _|p, 0xFFFFFFFF;\n\tselp.b32 %0, 1, 0, p;\n\t}" : "=r"(p));
    return p;
}

#define CP_ASYNC16(dst_u32, src_ptr) \
    asm volatile("cp.async.cg.shared.global [%0], [%1], 16;" :: "r"(dst_u32), "l"(src_ptr) : "memory")
#define CP_ASYNC_MBAR_ARRIVE(mbar) \
    asm volatile("cp.async.mbarrier.arrive.noinc.shared.b64 [%0];" :: "r"(mbar) : "memory")

#define MBARRIER_INIT(addr, cnt) \
    asm volatile("mbarrier.init.shared.b64 [%0], %1;" :: "r"(addr), "r"(cnt) : "memory")
#define MBARRIER_INVAL(addr) \
    asm volatile("mbarrier.inval.shared.b64 [%0];" :: "r"(addr) : "memory")
#define MBARRIER_WAIT_PARITY(addr, par) do {                                        \
    uint32_t _m = (addr), _p = (par), _d;                                           \
    asm volatile("{\n\t.reg .pred p;\n\t"                                           \
        "mbarrier.try_wait.parity.acquire.cta.shared::cta.b64 p, [%1], %2;\n\t"     \
        "selp.b32 %0, 1, 0, p;\n\t}" : "=r"(_d) : "r"(_m), "r"(_p) : "memory");     \
    if (!_d) {                                                                      \
        asm volatile("{\n\t.reg .pred P1;\n\t"                                      \
            "WL_%=:\n\t"                                                            \
            "mbarrier.try_wait.parity.acquire.cta.shared::cta.b64 P1, [%0], %1, 0x989680;\n\t" \
            "@P1 bra.uni WD_%=;\n\tbra.uni WL_%=;\n\tWD_%=:\n\t}"                   \
            :: "r"(_m), "r"(_p) : "memory");                                        \
    } } while (0)

#define TCGEN05_ALLOC(smem_addr, ncols) \
    asm volatile("tcgen05.alloc.cta_group::1.sync.aligned.shared::cta.b32 [%0], %1;" \
                 :: "r"(smem_addr), "r"(ncols) : "memory")
#define TCGEN05_DEALLOC(tmem, ncols) \
    asm volatile("tcgen05.dealloc.cta_group::1.sync.aligned.b32 %0, %1;" :: "r"(tmem), "r"(ncols))
#define TCGEN05_RELINQ() \
    asm volatile("tcgen05.relinquish_alloc_permit.cta_group::1.sync.aligned;")
#define TCGEN05_COMMIT(mbar) \
    asm volatile("tcgen05.commit.cta_group::1.mbarrier::arrive::one.shared::cluster.b64 [%0];" \
                 :: "r"(mbar) : "memory")
#define TCGEN05_FENCE_AFTER() \
    asm volatile("tcgen05.fence::after_thread_sync;" ::: "memory")
#define TCGEN05_FENCE_BEFORE() \
    asm volatile("tcgen05.fence::before_thread_sync;" ::: "memory")
#define TCGEN05_WAIT_LD() \
    asm volatile("tcgen05.wait::ld.sync.aligned;" ::: "memory")
#define FENCE_PROXY_ASYNC() \
    asm volatile("fence.proxy.async.shared::cta;" ::: "memory")

#define TCGEN05_LD_X32(r, tmem_addr) \
    asm volatile("tcgen05.ld.sync.aligned.32x32b.x32.b32 " \
        "{%0, %1, %2, %3, %4, %5, %6, %7, %8, %9, %10, %11, %12, %13, %14, %15, " \
        " %16, %17, %18, %19, %20, %21, %22, %23, %24, %25, %26, %27, %28, %29, %30, %31}, [%32];" \
        : "=r"((r)[0]),  "=r"((r)[1]),  "=r"((r)[2]),  "=r"((r)[3]),  \
          "=r"((r)[4]),  "=r"((r)[5]),  "=r"((r)[6]),  "=r"((r)[7]),  \
          "=r"((r)[8]),  "=r"((r)[9]),  "=r"((r)[10]), "=r"((r)[11]), \
          "=r"((r)[12]), "=r"((r)[13]), "=r"((r)[14]), "=r"((r)[15]), \
          "=r"((r)[16]), "=r"((r)[17]), "=r"((r)[18]), "=r"((r)[19]), \
          "=r"((r)[20]), "=r"((r)[21]), "=r"((r)[22]), "=r"((r)[23]), \
          "=r"((r)[24]), "=r"((r)[25]), "=r"((r)[26]), "=r"((r)[27]), \
          "=r"((r)[28]), "=r"((r)[29]), "=r"((r)[30]), "=r"((r)[31]) \
        : "r"(tmem_addr))

// SS-mode bf16 MMA, cta_group::1, fp32 accumulate in TMEM
__device__ __forceinline__ void mma_f16_ss(uint32_t d_tmem, uint64_t a_desc,
                                           uint64_t b_desc, uint32_t idesc, bool acc) {
    uint32_t en = acc ? 1u : 0u, z = 0u;
    asm volatile("{\n\t.reg .pred p;\n\tsetp.ne.u32 p, %5, 0;\n\t"
        "tcgen05.mma.cta_group::1.kind::f16 [%0], %1, %2, %3, {%4, %4, %4, %4}, p;\n\t}"
        :: "r"(d_tmem), "l"(a_desc), "l"(b_desc), "r"(idesc), "r"(z), "r"(en) : "memory");
}

// SW64 K-major descriptor: layout=4 (SW64), version=1, SBO=32 (512B = 8 rows x 64B), LBO=1
static __device__ __forceinline__ uint64_t make_desc_sw64(uint32_t addr) {
    const uint64_t BASE = (4ull << 61) | (1ull << 46) | (32ull << 32) | (1ull << 16);
    return BASE | ((uint64_t)(addr >> 4) & 0x3FFFull);
}

// idesc: F32 out, BF16 in, M=128, N=256
#define MMA_IDESC ((1u << 4) | (1u << 7) | (1u << 10) | ((256u / 8) << 17) | ((128u / 16) << 24))
#endif // HAS_TCGEN05

// ---------------------------------------------------------------------------
// Conversion: X fp32 -> (hi, lo) bf16
// ---------------------------------------------------------------------------
__global__ __launch_bounds__(256)
void convert_x_kernel(const float* __restrict__ X,
                      __nv_bfloat16* __restrict__ Xhi,
                      __nv_bfloat16* __restrict__ Xlo)
{
    int idx = blockIdx.x * 256 + threadIdx.x;       // float4 index
    float4 v = ((const float4*)X)[idx];
    __nv_bfloat16 h[4], l[4];
    float vv[4] = {v.x, v.y, v.z, v.w};
    #pragma unroll
    for (int i = 0; i < 4; ++i) {
        h[i] = __float2bfloat16(vv[i]);
        l[i] = __float2bfloat16(vv[i] - __bfloat162float(h[i]));
    }
    *(uint2*)(Xhi + (size_t)idx * 4) = *(uint2*)h;
    *(uint2*)(Xlo + (size_t)idx * 4) = *(uint2*)l;
}

// ---------------------------------------------------------------------------
// Conversion + transpose: W[e][k][n] fp32 -> Wt(hi/lo)[e][n][k] bf16
// ---------------------------------------------------------------------------
__global__ __launch_bounds__(256)
void convert_w_kernel(const float* __restrict__ W,
                      __nv_bfloat16* __restrict__ Whi,
                      __nv_bfloat16* __restrict__ Wlo)
{
    __shared__ float t[32][33];
    const int e  = blockIdx.z;
    const int k0 = blockIdx.y * 32;
    const int n0 = blockIdx.x * 32;
    const int tx = threadIdx.x & 31;
    const int ty = threadIdx.x >> 5;    // 0..7

    const float* Wp = W + (size_t)e * DIM * DIM;
    #pragma unroll
    for (int r = 0; r < 4; ++r) {
        int k = k0 + ty + 8 * r;
        t[ty + 8 * r][tx] = Wp[(size_t)k * DIM + n0 + tx];
    }
    __syncthreads();
    #pragma unroll
    for (int r = 0; r < 4; ++r) {
        int n = n0 + ty + 8 * r;
        float v = t[tx][ty + 8 * r];
        __nv_bfloat16 h = __float2bfloat16(v);
        __nv_bfloat16 l = __float2bfloat16(v - __bfloat162float(h));
        size_t off = (size_t)e * DIM * DIM + (size_t)n * DIM + k0 + tx;
        Whi[off] = h;
        Wlo[off] = l;
    }
}

// ---------------------------------------------------------------------------
// GEMM: per expert e, H = relu(X_e @ W_e + b_e), bf16x3 split.
//   sm_103a: warp-specialized pipeline. Tile M=256 N=256, K_CHUNK=32, 3 stages.
//   Warps 0-3 producers (coalesced cp.async -> full mbar), warp 4 MMA.
//   family image: trivial correct fallback (never selected on GB300).
// ---------------------------------------------------------------------------
#define NSTAGE      3
#define K_CHUNK     32
#define N_CHUNKS    32               // 1024 / 32
#define STAGE_BYTES 65536            // Ahi16K Alo16K Bhi16K Blo16K (256 rows x 64B each)
#define OFF_BIAS  (NSTAGE * STAGE_BYTES)       // 196608, 1KB
#define OFF_TPTR  (OFF_BIAS + 1024)
#define OFF_FULL  (OFF_TPTR + 16)              // 3 x 8B
#define OFF_EMPTY (OFF_FULL + 24)              // 3 x 8B
#define OFF_FINAL (OFF_EMPTY + 24)
#define SMEM_SIZE (OFF_FINAL + 8)

__global__ __launch_bounds__(256, 1)
void gemm_tc_kernel(const __nv_bfloat16* __restrict__ Xhi,
                    const __nv_bfloat16* __restrict__ Xlo,
                    const __nv_bfloat16* __restrict__ Whi,
                    const __nv_bfloat16* __restrict__ Wlo,
                    const float* __restrict__ bias,
                    float* __restrict__ H)
{
#if HAS_TCGEN05
    extern __shared__ __align__(1024) char smem[];
    const uint32_t sbase  = smem_u32(smem);
    const int e      = blockIdx.z;
    const int tile_n = blockIdx.x * 256;
    const int tile_m = blockIdx.y * 256;
    const int tid    = threadIdx.x;
    const int wid    = tid >> 5;
    const int lid    = tid & 31;

    if (wid == 0) {
        TCGEN05_ALLOC(sbase + OFF_TPTR, 512);
        TCGEN05_RELINQ();
    }
    if (tid == 0) {
        #pragma unroll
        for (int s = 0; s < NSTAGE; ++s) {
            MBARRIER_INIT(sbase + OFF_FULL  + s * 8, 128);  // 128 producer threads
            MBARRIER_INIT(sbase + OFF_EMPTY + s * 8, 1);    // one tcgen05.commit
        }
        MBARRIER_INIT(sbase + OFF_FINAL, 1);
    }
    ((float*)(smem + OFF_BIAS))[tid] = bias[e * DIM + tile_n + tid];
    __syncthreads();
    uint32_t tmem;
    asm volatile("ld.shared.b32 %0, [%1];" : "=r"(tmem) : "r"(sbase + OFF_TPTR));

    const __nv_bfloat16* Ah = Xhi + (size_t)(e * CAP + tile_m) * DIM;
    const __nv_bfloat16* Al = Xlo + (size_t)(e * CAP + tile_m) * DIM;
    const __nv_bfloat16* Bh = Whi + ((size_t)e * DIM + tile_n) * DIM;
    const __nv_bfloat16* Bl = Wlo + ((size_t)e * DIM + tile_n) * DIM;

    if (wid < 4) {
        // ------- producers: 128 threads, granule-linear mapping (coalesced).
        // Per tensor: 1024 granules (256 rows x 4 x 16B). Consecutive lanes ->
        // consecutive granules, so lanes 0-3 cover one row's 64B slice and a
        // warp-op touches 8 GMEM lines (minimum at this K-chunk).
        int st = 0, it = 0;
        for (int c = 0; c < N_CHUNKS; ++c) {
            if (c >= NSTAGE)
                MBARRIER_WAIT_PARITY(sbase + OFF_EMPTY + st * 8, (it - 1) & 1);
            const uint32_t bb = sbase + st * STAGE_BYTES;
            const size_t koff = (size_t)(c * K_CHUNK);
            #pragma unroll
            for (int tI = 0; tI < 4; ++tI) {
                const __nv_bfloat16* base = (tI == 0) ? Ah : (tI == 1) ? Al
                                          : (tI == 2) ? Bh : Bl;
                const uint32_t dstT = bb + tI * 16384;
                #pragma unroll
                for (int i = 0; i < 8; ++i) {
                    int g    = i * 128 + tid;           // 0..1023
                    int row  = g >> 2;
                    int cg   = g & 3;
                    int byte = row * 64 + cg * 16;
                    int sw   = byte ^ ((byte >> 3) & 0x30);   // SW64 swizzle
                    CP_ASYNC16(dstT + sw,
                               (const char*)(base + (size_t)row * DIM + koff) + cg * 16);
                }
            }
            CP_ASYNC_MBAR_ARRIVE(sbase + OFF_FULL + st * 8);
            if (++st == NSTAGE) { st = 0; ++it; }
        }
    } else if (wid == 4) {
        // ---------------- MMA warp (single elected thread)
        if (elect_one_pred()) {
            int st = 0, it = 0;
            for (int c = 0; c < N_CHUNKS; ++c) {
                MBARRIER_WAIT_PARITY(sbase + OFF_FULL + st * 8, it & 1);
                FENCE_PROXY_ASYNC();
                const uint32_t bb = sbase + st * STAGE_BYTES;
                uint64_t dAh = make_desc_sw64(bb + 0);
                uint64_t dAl = make_desc_sw64(bb + 16384);
                uint64_t dBh = make_desc_sw64(bb + 32768);
                uint64_t dBl = make_desc_sw64(bb + 49152);
                #pragma unroll
                for (int h = 0; h < 2; ++h) {
                    const uint32_t D   = tmem + h * 256;
                    const uint64_t hof = h * 512;             // 128 rows x 64B = 512 units
                    #pragma unroll
                    for (int kk = 0; kk < 2; ++kk) {
                        mma_f16_ss(D, dAh + hof + kk * 2, dBh + kk * 2, MMA_IDESC,
                                   !(c == 0 && kk == 0));
                        mma_f16_ss(D, dAh + hof + kk * 2, dBl + kk * 2, MMA_IDESC, true);
                        mma_f16_ss(D, dAl + hof + kk * 2, dBh + kk * 2, MMA_IDESC, true);
                    }
                }
                TCGEN05_COMMIT(sbase + OFF_EMPTY + st * 8);
                if (++st == NSTAGE) { st = 0; ++it; }
            }
            TCGEN05_COMMIT(sbase + OFF_FINAL);
        }
    }

    // ---------------- epilogue: all 8 warps after final MMA completes
    MBARRIER_WAIT_PARITY(sbase + OFF_FINAL, 0);
    TCGEN05_FENCE_AFTER();

    {
        const int half = wid >> 2, sub = wid & 3;
        const int row  = tile_m + half * 128 + sub * 32 + lid;
        float* outp = H + (size_t)(e * CAP + row) * DIM + tile_n;
        const float* bs = (const float*)(smem + OFF_BIAS);
        const uint32_t dbase = tmem + half * 256;
        #pragma unroll
        for (int base = 0; base < 256; base += 32) {
            uint32_t r[32];
            TCGEN05_LD_X32(r, dbase + base);
            TCGEN05_WAIT_LD();
            float v[32];
            #pragma unroll
            for (int i = 0; i < 32; ++i)
                v[i] = fmaxf(__uint_as_float(r[i]) + bs[base + i], 0.f);
            #pragma unroll
            for (int q = 0; q < 8; ++q)
                *(float4*)(outp + base + q * 4) = *(float4*)&v[q * 4];
        }
        TCGEN05_FENCE_BEFORE();
    }
    __syncthreads();
    if (tid == 0) {
        #pragma unroll
        for (int s = 0; s < NSTAGE; ++s) {
            MBARRIER_INVAL(sbase + OFF_FULL  + s * 8);
            MBARRIER_INVAL(sbase + OFF_EMPTY + s * 8);
        }
        MBARRIER_INVAL(sbase + OFF_FINAL);
    }
    __syncthreads();
    if (wid == 0) TCGEN05_DEALLOC(tmem, 512);

#else
    // ---------------- trivial correct fallback (family-level image; not used on GB300)
    const int e      = blockIdx.z;
    const int tile_n = blockIdx.x * 256;
    const int tile_m = blockIdx.y * 256;
    const int tid    = threadIdx.x;
    const int row    = tile_m + tid;
    const __nv_bfloat16* Ahp = Xhi + (size_t)(e * CAP + row) * DIM;
    const __nv_bfloat16* Alp = Xlo + (size_t)(e * CAP + row) * DIM;
    for (int n = 0; n < 256; ++n) {
        const __nv_bfloat16* Bhp = Whi + ((size_t)e * DIM + tile_n + n) * DIM;
        const __nv_bfloat16* Blp = Wlo + ((size_t)e * DIM + tile_n + n) * DIM;
        float s = 0.f;
        for (int k = 0; k < DIM; ++k) {
            float a = __bfloat162float(Ahp[k]) + __bfloat162float(Alp[k]);
            float b = __bfloat162float(Bhp[k]) + __bfloat162float(Blp[k]);
            s = fmaf(a, b, s);
        }
        s += bias[e * DIM + tile_n + n];
        H[(size_t)(e * CAP + row) * DIM + tile_n + n] = fmaxf(s, 0.f);
    }
#endif
}

// ---------------------------------------------------------------------------
// LayerNorm over D=1024 per row; one 256-thread CTA per token. (R3 version)
// ---------------------------------------------------------------------------
__global__ __launch_bounds__(256)
void layernorm_kernel(const float* __restrict__ H,
                      const float* __restrict__ gamma,
                      const float* __restrict__ beta,
                      float* __restrict__ out)
{
    const int row = blockIdx.x;
    const int e   = row >> 10;
    const int tid = threadIdx.x;

    const float* h = H + (size_t)row * DIM;
    float4 v = *(const float4*)(h + tid * 4);

    float s  = v.x + v.y + v.z + v.w;
    float sq = v.x * v.x + v.y * v.y + v.z * v.z + v.w * v.w;

    #pragma unroll
    for (int off = 16; off > 0; off >>= 1) {
        s  += __shfl_xor_sync(0xffffffffu, s,  off);
        sq += __shfl_xor_sync(0xffffffffu, sq, off);
    }

    __shared__ float red_s[8], red_q[8];
    const int wid = tid >> 5, lid = tid & 31;
    if (lid == 0) { red_s[wid] = s; red_q[wid] = sq; }
    __syncthreads();

    __shared__ float s_mean, s_rstd;
    if (wid == 0) {
        float ts = (lid < 8) ? red_s[lid] : 0.f;
        float tq = (lid < 8) ? red_q[lid] : 0.f;
        #pragma unroll
        for (int off = 4; off > 0; off >>= 1) {
            ts += __shfl_xor_sync(0xffffffffu, ts, off);
            tq += __shfl_xor_sync(0xffffffffu, tq, off);
        }
        if (lid == 0) {
            float mean = ts * (1.f / DIM);
            float var  = tq * (1.f / DIM) - mean * mean;
            s_mean = mean;
            s_rstd = rsqrtf(var + LN_EPS);
        }
    }
    __syncthreads();

    const float mean = s_mean, rstd = s_rstd;
    float4 g  = *(const float4*)(gamma + (size_t)e * DIM + tid * 4);
    float4 bt = *(const float4*)(beta  + (size_t)e * DIM + tid * 4);

    float4 o;
    o.x = (v.x - mean) * rstd * g.x + bt.x;
    o.y = (v.y - mean) * rstd * g.y + bt.y;
    o.z = (v.z - mean) * rstd * g.z + bt.z;
    o.w = (v.w - mean) * rstd * g.w + bt.w;
    *(float4*)(out + (size_t)row * DIM + tid * 4) = o;
}

// ---------------------------------------------------------------------------
extern "C" void kernel_launch(void* const* d_in, const int* in_sizes, int n_in,
                              void* d_out, int out_size)
{
    const float* x     = (const float*)d_in[0];
    // d_in[1] = expert_frequency (equal capacities) — unused
    const float* W     = (const float*)d_in[2];
    const float* bias  = (const float*)d_in[3];
    const float* gamma = (const float*)d_in[4];
    const float* beta  = (const float*)d_in[5];
    float*       out   = (float*)d_out;

    __nv_bfloat16 *xhi, *xlo, *whi, *wlo;
    float* h;
    cudaGetSymbolAddress((void**)&xhi, g_xhi);
    cudaGetSymbolAddress((void**)&xlo, g_xlo);
    cudaGetSymbolAddress((void**)&whi, g_whi);
    cudaGetSymbolAddress((void**)&wlo, g_wlo);
    cudaGetSymbolAddress((void**)&h,   g_h);

    static bool attr_done = false;
    if (!attr_done) {
        cudaFuncSetAttribute(gemm_tc_kernel,
                             cudaFuncAttributeMaxDynamicSharedMemorySize, SMEM_SIZE);
        attr_done = true;
    }

    convert_x_kernel<<<NTOK * DIM / (256 * 4), 256>>>(x, xhi, xlo);
    convert_w_kernel<<<dim3(DIM / 32, DIM / 32, NEXP), 256>>>(W, whi, wlo);

    dim3 grid(DIM / 256, CAP / 256, NEXP);  // 4 x 4 x 8 = 128 CTAs (one wave)
    gemm_tc_kernel<<<grid, 256, SMEM_SIZE>>>(xhi, xlo, whi, wlo, bias, h);

    layernorm_kernel<<<NTOK, 256>>>(h, gamma, beta, out);
}